// round 5
// baseline (speedup 1.0000x reference)
#include <cuda_runtime.h>
#include <cuda_bf16.h>
#include <cstdint>

#define STEPS 20
#define BATCH 512
#define DIM   2048
#define M_TOT (STEPS * BATCH)   // 10240
#define K_DIM DIM               // 2048
#define N_DIM DIM               // 2048

#define BM 128
#define BN 256
#define BK 64
#define NKITER (K_DIM / BK)      // 32
#define SROW 72                  // padded smem row stride (elements), 144 B
#define A_TILE_B (128 * SROW * 2)                // 18432
#define B_TILE_B (256 * SROW * 2)                // 36864
#define STAGE_B (A_TILE_B + 2 * B_TILE_B)        // 92160
#define NSTAGE 2
#define SMEM_TOTAL (NSTAGE * STAGE_B)            // 184320

// ---------------- device globals (no allocs allowed) ----------------
__device__ __align__(256) __nv_bfloat16 g_Xb[(size_t)M_TOT * K_DIM];  // 42 MB
__device__ __align__(256) __nv_bfloat16 g_Wh[(size_t)N_DIM * K_DIM];  // 8 MB
__device__ __align__(256) __nv_bfloat16 g_Wl[(size_t)N_DIM * K_DIM];  // 8 MB
__device__ __align__(256) float         g_J [(size_t)M_TOT * N_DIM];  // 84 MB

// ---------------- PTX helpers ----------------
__device__ __forceinline__ uint32_t smem_u32(const void* p) {
    uint32_t a;
    asm("{ .reg .u64 t; cvta.to.shared.u64 t, %1; cvt.u32.u64 %0, t; }" : "=r"(a) : "l"(p));
    return a;
}
__device__ __forceinline__ void cp16(uint32_t s, const void* g) {
    asm volatile("cp.async.cg.shared.global [%0], [%1], 16;" :: "r"(s), "l"(g));
}
#define CP_COMMIT() asm volatile("cp.async.commit_group;" ::: "memory")

#define LDMX4(r0, r1, r2, r3, a) \
    asm volatile("ldmatrix.sync.aligned.m8n8.x4.shared.b16 {%0,%1,%2,%3}, [%4];" \
                 : "=r"(r0), "=r"(r1), "=r"(r2), "=r"(r3) : "r"(a))

#define MMA16816(c, a0, a1, a2, a3, b0, b1) \
    asm volatile("mma.sync.aligned.m16n8k16.row.col.f32.bf16.bf16.f32 " \
                 "{%0,%1,%2,%3}, {%4,%5,%6,%7}, {%8,%9}, {%0,%1,%2,%3};" \
                 : "+f"((c)[0]), "+f"((c)[1]), "+f"((c)[2]), "+f"((c)[3]) \
                 : "r"(a0), "r"(a1), "r"(a2), "r"(a3), "r"(b0), "r"(b1))

// ---------------- conversion kernels ----------------
__global__ __launch_bounds__(256) void conv_x_kernel(const float* __restrict__ x) {
    size_t i = ((size_t)blockIdx.x * 256 + threadIdx.x) * 4;
    float4 v = *reinterpret_cast<const float4*>(x + i);
    *reinterpret_cast<__nv_bfloat162*>(g_Xb + i)     = __floats2bfloat162_rn(v.x, v.y);
    *reinterpret_cast<__nv_bfloat162*>(g_Xb + i + 2) = __floats2bfloat162_rn(v.z, v.w);
}

__global__ __launch_bounds__(256) void conv_w_kernel(const float* __restrict__ w) {
    size_t i = ((size_t)blockIdx.x * 256 + threadIdx.x) * 4;
    float4 v = *reinterpret_cast<const float4*>(w + i);
    __nv_bfloat16 h0 = __float2bfloat16(v.x), h1 = __float2bfloat16(v.y);
    __nv_bfloat16 h2 = __float2bfloat16(v.z), h3 = __float2bfloat16(v.w);
    __nv_bfloat162 hi01; hi01.x = h0; hi01.y = h1;
    __nv_bfloat162 hi23; hi23.x = h2; hi23.y = h3;
    *reinterpret_cast<__nv_bfloat162*>(g_Wh + i)     = hi01;
    *reinterpret_cast<__nv_bfloat162*>(g_Wh + i + 2) = hi23;
    *reinterpret_cast<__nv_bfloat162*>(g_Wl + i) =
        __floats2bfloat162_rn(v.x - __bfloat162float(h0), v.y - __bfloat162float(h1));
    *reinterpret_cast<__nv_bfloat162*>(g_Wl + i + 2) =
        __floats2bfloat162_rn(v.z - __bfloat162float(h2), v.w - __bfloat162float(h3));
}

// ---------------- HMMA GEMM: J = Xb @ (Wh + Wl)^T ----------------
// Block 128x256x64, 8 warps (2m x 4n), warp tile 64x64, frags m16n8k16.
// 2-stage cp.async double buffer, prefetch distance 1.
__global__ __launch_bounds__(256, 1) void gemm_hmma_kernel() {
    extern __shared__ char smem[];
    const uint32_t sbase = smem_u32(smem);

    const int tid = threadIdx.x;
    const int wid = tid >> 5;
    const int lid = tid & 31;
    const int wm = wid & 1;          // 0..1  (m slices of 64)
    const int wn = wid >> 1;         // 0..3  (n slices of 64)
    const int bn = blockIdx.x;       // 0..7
    const int bm = blockIdx.y;       // 0..79

    const __nv_bfloat16* Ag = g_Xb + (size_t)(bm * BM) * K_DIM;
    const __nv_bfloat16* Hg = g_Wh + (size_t)(bn * BN) * K_DIM;
    const __nv_bfloat16* Lg = g_Wl + (size_t)(bn * BN) * K_DIM;

    auto sA = [&](int s) { return sbase + s * STAGE_B; };
    auto sH = [&](int s) { return sbase + s * STAGE_B + A_TILE_B; };
    auto sL = [&](int s) { return sbase + s * STAGE_B + A_TILE_B + B_TILE_B; };

    // global->smem: A 128x8 chunks(16B)=1024, Bh 2048, Bl 2048; 256 thr.
    auto load_stage = [&](int s, int kt) {
        const int kof = kt * BK;
        const uint32_t a = sA(s), h = sH(s), l = sL(s);
#pragma unroll
        for (int it = 0; it < 4; it++) {              // A: 1024 chunks
            const int c = tid + it * 256;
            const int r = c >> 3;
            const int cb = (c & 7) * 16;
            cp16(a + r * (SROW * 2) + cb, Ag + (size_t)r * K_DIM + kof + cb / 2);
        }
#pragma unroll
        for (int it = 0; it < 8; it++) {              // Bh + Bl: 2048 chunks each
            const int c = tid + it * 256;
            const int r = c >> 3;
            const int cb = (c & 7) * 16;
            const uint32_t so = r * (SROW * 2) + cb;
            const size_t  go = (size_t)r * K_DIM + kof + cb / 2;
            cp16(h + so, Hg + go);
            cp16(l + so, Lg + go);
        }
        CP_COMMIT();
    };

    float acc[4][8][4];
#pragma unroll
    for (int i = 0; i < 4; i++)
#pragma unroll
        for (int j = 0; j < 8; j++)
#pragma unroll
            for (int r = 0; r < 4; r++) acc[i][j][r] = 0.0f;

    // ldmatrix per-thread components
    const int a_row = wm * 64 + (lid & 15);                      // + mi*16
    const int a_ke  = (lid >> 4) * 8;                            // + ks*16 (elements)
    const int b_row = wn * 64 + (lid & 7) + ((lid >> 4) << 3);   // + nj2*16
    const int b_ke  = ((lid >> 3) & 1) * 8;                      // + ks*16 (elements)

    load_stage(0, 0);

    for (int kt = 0; kt < NKITER; kt++) {
        if (kt + 1 < NKITER) {
            load_stage((kt + 1) & 1, kt + 1);
            asm volatile("cp.async.wait_group 1;" ::: "memory");
        } else {
            asm volatile("cp.async.wait_group 0;" ::: "memory");
        }
        __syncthreads();

        const int s = kt & 1;
        const uint32_t aT = sA(s), hT = sH(s), lT = sL(s);

#pragma unroll
        for (int ks = 0; ks < 4; ks++) {
            uint32_t af[4][4];
#pragma unroll
            for (int mi = 0; mi < 4; mi++) {
                uint32_t addr = aT + (a_row + mi * 16) * (SROW * 2) + (a_ke + ks * 16) * 2;
                LDMX4(af[mi][0], af[mi][1], af[mi][2], af[mi][3], addr);
            }
#pragma unroll
            for (int nj2 = 0; nj2 < 4; nj2++) {
                uint32_t b0, b1, b2, b3;
                uint32_t addr = hT + (b_row + nj2 * 16) * (SROW * 2) + (b_ke + ks * 16) * 2;
                LDMX4(b0, b1, b2, b3, addr);
#pragma unroll
                for (int mi = 0; mi < 4; mi++) {
                    MMA16816(acc[mi][nj2 * 2],     af[mi][0], af[mi][1], af[mi][2], af[mi][3], b0, b1);
                    MMA16816(acc[mi][nj2 * 2 + 1], af[mi][0], af[mi][1], af[mi][2], af[mi][3], b2, b3);
                }
                addr = lT + (b_row + nj2 * 16) * (SROW * 2) + (b_ke + ks * 16) * 2;
                LDMX4(b0, b1, b2, b3, addr);
#pragma unroll
                for (int mi = 0; mi < 4; mi++) {
                    MMA16816(acc[mi][nj2 * 2],     af[mi][0], af[mi][1], af[mi][2], af[mi][3], b0, b1);
                    MMA16816(acc[mi][nj2 * 2 + 1], af[mi][0], af[mi][1], af[mi][2], af[mi][3], b2, b3);
                }
            }
        }
        __syncthreads();   // retire stage s before the next prefetch overwrites it
    }

    // epilogue
    const int mrow0 = bm * BM + wm * 64 + (lid >> 2);
    const int ncol0 = bn * BN + wn * 64 + (lid & 3) * 2;
#pragma unroll
    for (int mi = 0; mi < 4; mi++) {
#pragma unroll
        for (int nj = 0; nj < 8; nj++) {
            float* p0 = g_J + (size_t)(mrow0 + mi * 16) * N_DIM + ncol0 + nj * 8;
            float* p1 = g_J + (size_t)(mrow0 + mi * 16 + 8) * N_DIM + ncol0 + nj * 8;
            *reinterpret_cast<float2*>(p0) = make_float2(acc[mi][nj][0], acc[mi][nj][1]);
            *reinterpret_cast<float2*>(p1) = make_float2(acc[mi][nj][2], acc[mi][nj][3]);
        }
    }
}

// ---------------- LIF scan (float4 vectorized) ----------------
__global__ __launch_bounds__(256) void lif_scan_kernel(float* __restrict__ out) {
    const size_t idx4 = ((size_t)blockIdx.x * 256 + threadIdx.x) * 4;
    const size_t stride = (size_t)BATCH * DIM;
    float V[4] = {0, 0, 0, 0}, I[4] = {0, 0, 0, 0};
#pragma unroll
    for (int t = 0; t < STEPS; t++) {
        float4 j = *reinterpret_cast<const float4*>(g_J + (size_t)t * stride + idx4);
        float4 s4;
        float jj[4] = {j.x, j.y, j.z, j.w};
        float ss[4];
#pragma unroll
        for (int e = 0; e < 4; e++) {
            float Vn = 0.95f * V[e] + 0.05f * I[e];
            float s = (Vn >= 1.0f) ? 1.0f : 0.0f;
            V[e] = Vn * (1.0f - s);
            I[e] = 0.8f * I[e] + jj[e];
            ss[e] = s;
        }
        s4.x = ss[0]; s4.y = ss[1]; s4.z = ss[2]; s4.w = ss[3];
        *reinterpret_cast<float4*>(out + (size_t)t * stride + idx4) = s4;
    }
}

// ---------------- launch ----------------
extern "C" void kernel_launch(void* const* d_in, const int* in_sizes, int n_in,
                              void* d_out, int out_size) {
    const float* x = (const float*)d_in[0];   // [20, 512, 2048]
    const float* W = (const float*)d_in[1];   // [2048, 2048]
    float* out = (float*)d_out;

    conv_x_kernel<<<(M_TOT * K_DIM) / (256 * 4), 256>>>(x);
    conv_w_kernel<<<(N_DIM * K_DIM) / (256 * 4), 256>>>(W);

    cudaFuncSetAttribute(gemm_hmma_kernel,
                         cudaFuncAttributeMaxDynamicSharedMemorySize, SMEM_TOTAL);
    gemm_hmma_kernel<<<dim3(N_DIM / BN, M_TOT / BM), 256, SMEM_TOTAL>>>();

    lif_scan_kernel<<<(BATCH * DIM) / (256 * 4), 256>>>(out);
}

// round 6
// speedup vs baseline: 1.1973x; 1.1973x over previous
#include <cuda_runtime.h>
#include <cuda_bf16.h>
#include <cstdint>

#define STEPS 20
#define BATCH 512
#define DIM   2048
#define M_TOT (STEPS * BATCH)   // 10240
#define K_DIM DIM               // 2048
#define N_DIM DIM               // 2048

#define BM 128
#define BN 128
#define BK 64
#define NKITER (K_DIM / BK)      // 32
#define SROW 72                  // padded smem row stride (elements), 144 B
#define TILE_B (128 * SROW * 2)  // 18432 B per 128x64 bf16 tile
#define STAGE_B (3 * TILE_B)     // A + Bh + Bl = 55296 B
#define NSTAGE 2
#define SMEM_TOTAL (NSTAGE * STAGE_B)            // 110592 B -> 2 CTA/SM

// ---------------- device globals (no allocs allowed) ----------------
__device__ __align__(256) __nv_bfloat16 g_Xb[(size_t)M_TOT * K_DIM];  // 42 MB
__device__ __align__(256) __nv_bfloat16 g_Wh[(size_t)N_DIM * K_DIM];  // 8 MB
__device__ __align__(256) __nv_bfloat16 g_Wl[(size_t)N_DIM * K_DIM];  // 8 MB
__device__ __align__(256) float         g_J [(size_t)M_TOT * N_DIM];  // 84 MB

// ---------------- PTX helpers ----------------
__device__ __forceinline__ uint32_t smem_u32(const void* p) {
    uint32_t a;
    asm("{ .reg .u64 t; cvta.to.shared.u64 t, %1; cvt.u32.u64 %0, t; }" : "=r"(a) : "l"(p));
    return a;
}
__device__ __forceinline__ void cp16(uint32_t s, const void* g) {
    asm volatile("cp.async.cg.shared.global [%0], [%1], 16;" :: "r"(s), "l"(g));
}
#define CP_COMMIT() asm volatile("cp.async.commit_group;" ::: "memory")

#define LDMX4(r0, r1, r2, r3, a) \
    asm volatile("ldmatrix.sync.aligned.m8n8.x4.shared.b16 {%0,%1,%2,%3}, [%4];" \
                 : "=r"(r0), "=r"(r1), "=r"(r2), "=r"(r3) : "r"(a))

#define MMA16816(c, a0, a1, a2, a3, b0, b1) \
    asm volatile("mma.sync.aligned.m16n8k16.row.col.f32.bf16.bf16.f32 " \
                 "{%0,%1,%2,%3}, {%4,%5,%6,%7}, {%8,%9}, {%0,%1,%2,%3};" \
                 : "+f"((c)[0]), "+f"((c)[1]), "+f"((c)[2]), "+f"((c)[3]) \
                 : "r"(a0), "r"(a1), "r"(a2), "r"(a3), "r"(b0), "r"(b1))

// ---------------- fused conversion kernel ----------------
// blocks [0, XB): convert X fp32 -> bf16
// blocks [XB, XB+WB): split W fp32 -> bf16 hi + bf16 lo
#define XQ ((size_t)M_TOT * K_DIM / 4)   // 5242880 quads
#define WQ ((size_t)N_DIM * K_DIM / 4)   // 1048576 quads
#define XB (XQ / 256)                    // 20480 blocks
#define WB (WQ / 256)                    // 4096 blocks
__global__ __launch_bounds__(256) void conv_fused_kernel(const float* __restrict__ x,
                                                         const float* __restrict__ w) {
    if (blockIdx.x < XB) {
        size_t i = ((size_t)blockIdx.x * 256 + threadIdx.x) * 4;
        float4 v = *reinterpret_cast<const float4*>(x + i);
        *reinterpret_cast<__nv_bfloat162*>(g_Xb + i)     = __floats2bfloat162_rn(v.x, v.y);
        *reinterpret_cast<__nv_bfloat162*>(g_Xb + i + 2) = __floats2bfloat162_rn(v.z, v.w);
    } else {
        size_t i = (((size_t)blockIdx.x - XB) * 256 + threadIdx.x) * 4;
        float4 v = *reinterpret_cast<const float4*>(w + i);
        __nv_bfloat16 h0 = __float2bfloat16(v.x), h1 = __float2bfloat16(v.y);
        __nv_bfloat16 h2 = __float2bfloat16(v.z), h3 = __float2bfloat16(v.w);
        __nv_bfloat162 hi01; hi01.x = h0; hi01.y = h1;
        __nv_bfloat162 hi23; hi23.x = h2; hi23.y = h3;
        *reinterpret_cast<__nv_bfloat162*>(g_Wh + i)     = hi01;
        *reinterpret_cast<__nv_bfloat162*>(g_Wh + i + 2) = hi23;
        *reinterpret_cast<__nv_bfloat162*>(g_Wl + i) =
            __floats2bfloat162_rn(v.x - __bfloat162float(h0), v.y - __bfloat162float(h1));
        *reinterpret_cast<__nv_bfloat162*>(g_Wl + i + 2) =
            __floats2bfloat162_rn(v.z - __bfloat162float(h2), v.w - __bfloat162float(h3));
    }
}

// ---------------- HMMA GEMM: J = Xb @ (Wh + Wl)^T ----------------
// Block 128x128x64, 8 warps (2m x 4n), warp tile 64x32, frags m16n8k16.
// 2-stage double buffer; ONE sync per iteration:
//   wait_group 0 -> syncthreads -> prefetch(kt+1) -> compute(kt)
// The top barrier retires stage (kt+1)&1 (it was computed at kt-1), making
// the prefetch write safe and moving cp.async issue into the MMA shadow.
__global__ __launch_bounds__(256, 2) void gemm_hmma_kernel() {
    extern __shared__ char smem[];
    const uint32_t sbase = smem_u32(smem);

    const int tid = threadIdx.x;
    const int wid = tid >> 5;
    const int lid = tid & 31;
    const int wm = wid & 1;          // 0..1  (m slices of 64)
    const int wn = wid >> 1;         // 0..3  (n slices of 32)
    const int bn = blockIdx.x;       // 0..15
    const int bm = blockIdx.y;       // 0..79

    const __nv_bfloat16* Ag = g_Xb + (size_t)(bm * BM) * K_DIM;
    const __nv_bfloat16* Hg = g_Wh + (size_t)(bn * BN) * K_DIM;
    const __nv_bfloat16* Lg = g_Wl + (size_t)(bn * BN) * K_DIM;

    auto sA = [&](int s) { return sbase + s * STAGE_B; };
    auto sH = [&](int s) { return sbase + s * STAGE_B + TILE_B; };
    auto sL = [&](int s) { return sbase + s * STAGE_B + 2 * TILE_B; };

    // global->smem: tile = 128 rows x 8 chunks(16B) = 1024 chunks; 4 per thread.
    auto load_stage = [&](int s, int kt) {
        const int kof = kt * BK;
        const uint32_t a = sA(s), h = sH(s), l = sL(s);
#pragma unroll
        for (int it = 0; it < 4; it++) {
            const int c = tid + it * 256;
            const int r = c >> 3;
            const int cb = (c & 7) * 16;
            const uint32_t so = r * (SROW * 2) + cb;
            const size_t  go = (size_t)r * K_DIM + kof + cb / 2;
            cp16(a + so, Ag + go);
            cp16(h + so, Hg + go);
            cp16(l + so, Lg + go);
        }
        CP_COMMIT();
    };

    float acc[4][4][4];
#pragma unroll
    for (int i = 0; i < 4; i++)
#pragma unroll
        for (int j = 0; j < 4; j++)
#pragma unroll
            for (int r = 0; r < 4; r++) acc[i][j][r] = 0.0f;

    // ldmatrix per-thread components
    const int a_row = wm * 64 + (lid & 15);                      // + mi*16
    const int a_ke  = (lid >> 4) * 8;                            // + ks*16 (elements)
    const int b_row = wn * 32 + (lid & 7) + ((lid >> 4) << 3);   // + nj2*16
    const int b_ke  = ((lid >> 3) & 1) * 8;                      // + ks*16 (elements)

    load_stage(0, 0);

    for (int kt = 0; kt < NKITER; kt++) {
        asm volatile("cp.async.wait_group 0;" ::: "memory");
        __syncthreads();
        if (kt + 1 < NKITER) load_stage((kt + 1) & 1, kt + 1);

        const int s = kt & 1;
        const uint32_t aT = sA(s), hT = sH(s), lT = sL(s);

#pragma unroll
        for (int ks = 0; ks < 4; ks++) {
            uint32_t af[4][4];
#pragma unroll
            for (int mi = 0; mi < 4; mi++) {
                uint32_t addr = aT + (a_row + mi * 16) * (SROW * 2) + (a_ke + ks * 16) * 2;
                LDMX4(af[mi][0], af[mi][1], af[mi][2], af[mi][3], addr);
            }
#pragma unroll
            for (int nj2 = 0; nj2 < 2; nj2++) {
                uint32_t b0, b1, b2, b3;
                uint32_t addr = hT + (b_row + nj2 * 16) * (SROW * 2) + (b_ke + ks * 16) * 2;
                LDMX4(b0, b1, b2, b3, addr);
#pragma unroll
                for (int mi = 0; mi < 4; mi++) {
                    MMA16816(acc[mi][nj2 * 2],     af[mi][0], af[mi][1], af[mi][2], af[mi][3], b0, b1);
                    MMA16816(acc[mi][nj2 * 2 + 1], af[mi][0], af[mi][1], af[mi][2], af[mi][3], b2, b3);
                }
                addr = lT + (b_row + nj2 * 16) * (SROW * 2) + (b_ke + ks * 16) * 2;
                LDMX4(b0, b1, b2, b3, addr);
#pragma unroll
                for (int mi = 0; mi < 4; mi++) {
                    MMA16816(acc[mi][nj2 * 2],     af[mi][0], af[mi][1], af[mi][2], af[mi][3], b0, b1);
                    MMA16816(acc[mi][nj2 * 2 + 1], af[mi][0], af[mi][1], af[mi][2], af[mi][3], b2, b3);
                }
            }
        }
    }

    // epilogue
    const int mrow0 = bm * BM + wm * 64 + (lid >> 2);
    const int ncol0 = bn * BN + wn * 32 + (lid & 3) * 2;
#pragma unroll
    for (int mi = 0; mi < 4; mi++) {
#pragma unroll
        for (int nj = 0; nj < 4; nj++) {
            float* p0 = g_J + (size_t)(mrow0 + mi * 16) * N_DIM + ncol0 + nj * 8;
            float* p1 = g_J + (size_t)(mrow0 + mi * 16 + 8) * N_DIM + ncol0 + nj * 8;
            *reinterpret_cast<float2*>(p0) = make_float2(acc[mi][nj][0], acc[mi][nj][1]);
            *reinterpret_cast<float2*>(p1) = make_float2(acc[mi][nj][2], acc[mi][nj][3]);
        }
    }
}

// ---------------- LIF scan (float4 vectorized) ----------------
__global__ __launch_bounds__(256) void lif_scan_kernel(float* __restrict__ out) {
    const size_t idx4 = ((size_t)blockIdx.x * 256 + threadIdx.x) * 4;
    const size_t stride = (size_t)BATCH * DIM;
    float V[4] = {0, 0, 0, 0}, I[4] = {0, 0, 0, 0};
#pragma unroll
    for (int t = 0; t < STEPS; t++) {
        float4 j = *reinterpret_cast<const float4*>(g_J + (size_t)t * stride + idx4);
        float jj[4] = {j.x, j.y, j.z, j.w};
        float ss[4];
#pragma unroll
        for (int e = 0; e < 4; e++) {
            float Vn = 0.95f * V[e] + 0.05f * I[e];
            float s = (Vn >= 1.0f) ? 1.0f : 0.0f;
            V[e] = Vn * (1.0f - s);
            I[e] = 0.8f * I[e] + jj[e];
            ss[e] = s;
        }
        float4 s4; s4.x = ss[0]; s4.y = ss[1]; s4.z = ss[2]; s4.w = ss[3];
        *reinterpret_cast<float4*>(out + (size_t)t * stride + idx4) = s4;
    }
}

// ---------------- launch ----------------
extern "C" void kernel_launch(void* const* d_in, const int* in_sizes, int n_in,
                              void* d_out, int out_size) {
    const float* x = (const float*)d_in[0];   // [20, 512, 2048]
    const float* W = (const float*)d_in[1];   // [2048, 2048]
    float* out = (float*)d_out;

    conv_fused_kernel<<<XB + WB, 256>>>(x, W);

    cudaFuncSetAttribute(gemm_hmma_kernel,
                         cudaFuncAttributeMaxDynamicSharedMemorySize, SMEM_TOTAL);
    gemm_hmma_kernel<<<dim3(N_DIM / BN, M_TOT / BM), 256, SMEM_TOTAL>>>();

    lif_scan_kernel<<<(BATCH * DIM) / (256 * 4), 256>>>(out);
}